// round 6
// baseline (speedup 1.0000x reference)
#include <cuda_runtime.h>
#include <cuda_bf16.h>

constexpr int Bb = 16, Ss = 64, Nn = 2048, Ee = 256;
constexpr int KSPLIT = 16;

__device__ float g_Q[Bb * Nn * Ee];
__device__ float g_K[Bb * Nn * Ee];
__device__ float g_E[(size_t)Bb * Nn * Nn];
__device__ float g_cs[Bb * Nn];
__device__ float g_xn[Bb * Ss * Nn];
__device__ float g_AGG[Ss * Bb * Nn];
__device__ float g_part[3 * KSPLIT * Bb * Nn];
__device__ float g_h[Bb * Nn];

// ---------------- K0: zero cs, h, AGG ----------------
__global__ void k0_zero() {
    int idx = blockIdx.x * 256 + threadIdx.x;
    if (idx < Bb * Nn) { g_cs[idx] = 0.f; g_h[idx] = 0.f; }
    if (idx < Ss * Bb * Nn) g_AGG[idx] = 0.f;
}

// ---------------- K1: Q,K projection -----------------
// Q[b,n,e] = sum_s x[b,s,n]*Wq[e,s] + bq[e]; tile 128n x 64e, K=64.
__global__ __launch_bounds__(256) void k1_qk(
    const float* __restrict__ x,
    const float* __restrict__ Wq, const float* __restrict__ bq,
    const float* __restrict__ Wk, const float* __restrict__ bk)
{
    __shared__ float As[16][132];
    __shared__ float wqs[64][16];
    __shared__ float wks[64][16];
    int tid = threadIdx.x;
    int b = blockIdx.z, nbase = blockIdx.x * 128, ebase = blockIdx.y * 64;
    int tn = tid % 16, te = tid / 16;

    float4 accq[8], acck[8];
    #pragma unroll
    for (int i = 0; i < 8; ++i) { accq[i] = make_float4(0,0,0,0); acck[i] = make_float4(0,0,0,0); }

    for (int kc = 0; kc < 4; ++kc) {
        int kbase = kc * 16;
        #pragma unroll
        for (int p = 0; p < 2; ++p) {
            int v = tid + 256 * p;
            int k = v / 32, mq = v % 32;
            *(float4*)&As[k][mq * 4] =
                *(const float4*)&x[((size_t)(b * Ss + kbase + k)) * Nn + nbase + mq * 4];
        }
        {
            int e = tid / 4, kq = tid % 4;
            *(float4*)&wqs[e][kq * 4] = *(const float4*)&Wq[(ebase + e) * Ss + kbase + kq * 4];
            *(float4*)&wks[e][kq * 4] = *(const float4*)&Wk[(ebase + e) * Ss + kbase + kq * 4];
        }
        __syncthreads();
        #pragma unroll
        for (int kk = 0; kk < 16; ++kk) {
            float4 alo = *(float4*)&As[kk][tn * 8];
            float4 ahi = *(float4*)&As[kk][tn * 8 + 4];
            float av[8] = {alo.x, alo.y, alo.z, alo.w, ahi.x, ahi.y, ahi.z, ahi.w};
            float wq0 = wqs[te*4+0][kk], wq1 = wqs[te*4+1][kk];
            float wq2 = wqs[te*4+2][kk], wq3 = wqs[te*4+3][kk];
            float wk0 = wks[te*4+0][kk], wk1 = wks[te*4+1][kk];
            float wk2 = wks[te*4+2][kk], wk3 = wks[te*4+3][kk];
            #pragma unroll
            for (int i = 0; i < 8; ++i) {
                accq[i].x += av[i]*wq0; accq[i].y += av[i]*wq1;
                accq[i].z += av[i]*wq2; accq[i].w += av[i]*wq3;
                acck[i].x += av[i]*wk0; acck[i].y += av[i]*wk1;
                acck[i].z += av[i]*wk2; acck[i].w += av[i]*wk3;
            }
        }
        __syncthreads();
    }
    float4 bq4 = *(const float4*)&bq[ebase + te * 4];
    float4 bk4 = *(const float4*)&bk[ebase + te * 4];
    #pragma unroll
    for (int i = 0; i < 8; ++i) {
        int n = nbase + tn * 8 + i;
        size_t o = ((size_t)(b * Nn + n)) * Ee + ebase + te * 4;
        float4 q = accq[i]; q.x += bq4.x; q.y += bq4.y; q.z += bq4.z; q.w += bq4.w;
        float4 kk4 = acck[i]; kk4.x += bk4.x; kk4.y += bk4.y; kk4.z += bk4.z; kk4.w += bk4.w;
        *(float4*)&g_Q[o] = q;
        *(float4*)&g_K[o] = kk4;
    }
}

// ---------------- K2: scores + mask + exp + colsum ----------------
// E[b,i,j] = adj[i,j]>0 ? exp(Q[b,i,:].K[b,j,:]) : 0 ; cs[b,j] += col sum.
__global__ __launch_bounds__(256) void k2_scores(const int* __restrict__ adj)
{
    __shared__ float As[16][132];
    __shared__ float Bs[16][132];
    int tid = threadIdx.x;
    int b = blockIdx.z, mbase = blockIdx.y * 128, nbase = blockIdx.x * 128;
    int tx = tid % 16, ty = tid / 16;

    const float* Qb = g_Q + (size_t)b * Nn * Ee;
    const float* Kb = g_K + (size_t)b * Nn * Ee;

    float c[8][8];
    #pragma unroll
    for (int i = 0; i < 8; ++i)
        #pragma unroll
        for (int j = 0; j < 8; ++j) c[i][j] = 0.f;

    for (int kc = 0; kc < 16; ++kc) {
        int kbase = kc * 16;
        #pragma unroll
        for (int p = 0; p < 2; ++p) {
            int v = tid + 256 * p;
            int m = v / 4, kq = v % 4;
            float4 a4 = *(const float4*)&Qb[(size_t)(mbase + m) * Ee + kbase + kq * 4];
            As[kq*4+0][m] = a4.x; As[kq*4+1][m] = a4.y; As[kq*4+2][m] = a4.z; As[kq*4+3][m] = a4.w;
            float4 b4 = *(const float4*)&Kb[(size_t)(nbase + m) * Ee + kbase + kq * 4];
            Bs[kq*4+0][m] = b4.x; Bs[kq*4+1][m] = b4.y; Bs[kq*4+2][m] = b4.z; Bs[kq*4+3][m] = b4.w;
        }
        __syncthreads();
        #pragma unroll
        for (int kk = 0; kk < 16; ++kk) {
            float4 alo = *(float4*)&As[kk][ty * 8];
            float4 ahi = *(float4*)&As[kk][ty * 8 + 4];
            float4 blo = *(float4*)&Bs[kk][tx * 8];
            float4 bhi = *(float4*)&Bs[kk][tx * 8 + 4];
            float av[8] = {alo.x, alo.y, alo.z, alo.w, ahi.x, ahi.y, ahi.z, ahi.w};
            float bv[8] = {blo.x, blo.y, blo.z, blo.w, bhi.x, bhi.y, bhi.z, bhi.w};
            #pragma unroll
            for (int i = 0; i < 8; ++i)
                #pragma unroll
                for (int j = 0; j < 8; ++j) c[i][j] += av[i] * bv[j];
        }
        __syncthreads();
    }

    float csum[8];
    #pragma unroll
    for (int j = 0; j < 8; ++j) csum[j] = 0.f;

    #pragma unroll
    for (int i = 0; i < 8; ++i) {
        int gi = mbase + ty * 8 + i;
        const int* adjrow = adj + (size_t)gi * Nn + nbase + tx * 8;
        float* Erow = g_E + ((size_t)(b * Nn + gi)) * Nn + nbase + tx * 8;
        #pragma unroll
        for (int jv = 0; jv < 2; ++jv) {
            int4 a4 = *(const int4*)&adjrow[jv * 4];
            float4 e4;
            e4.x = (a4.x > 0) ? __expf(c[i][jv*4+0]) : 0.f;
            e4.y = (a4.y > 0) ? __expf(c[i][jv*4+1]) : 0.f;
            e4.z = (a4.z > 0) ? __expf(c[i][jv*4+2]) : 0.f;
            e4.w = (a4.w > 0) ? __expf(c[i][jv*4+3]) : 0.f;
            *(float4*)&Erow[jv * 4] = e4;
            csum[jv*4+0] += e4.x; csum[jv*4+1] += e4.y;
            csum[jv*4+2] += e4.z; csum[jv*4+3] += e4.w;
        }
    }
    #pragma unroll
    for (int j = 0; j < 8; ++j)
        atomicAdd(&g_cs[b * Nn + nbase + tx * 8 + j], csum[j]);
}

// ---------------- K3: xn = x / colsum ----------------
__global__ void k3_xn(const float* __restrict__ x) {
    int idx = blockIdx.x * 256 + threadIdx.x;
    if (idx < Bb * Ss * Nn) {
        int j = idx % Nn;
        int b = idx / (Ss * Nn);
        g_xn[idx] = x[idx] / g_cs[b * Nn + j];
    }
}

// ---------------- K4: AGG[t][b][i] = sum_j E[b,i,j]*xn[b,t,j] ----------------
// tile 128i x 64t, j split in 2, chunks of 32. atomics accumulate across jsplit.
__global__ __launch_bounds__(256) void k4_agg()
{
    __shared__ float es[32][132];
    __shared__ float xs[32][68];
    int tid = threadIdx.x;
    int b = blockIdx.z, ibase = blockIdx.x * 128, jsp = blockIdx.y;
    int it = tid % 16, tt = tid / 16;

    const float* Eb = g_E + ((size_t)b * Nn + ibase) * Nn;
    const float* xb = g_xn + (size_t)b * Ss * Nn;

    float4 acc[8];
    #pragma unroll
    for (int i = 0; i < 8; ++i) acc[i] = make_float4(0,0,0,0);

    for (int jc = 0; jc < 32; ++jc) {
        int jbase = jsp * 1024 + jc * 32;
        #pragma unroll
        for (int p = 0; p < 4; ++p) {
            int v = tid + 256 * p;
            int i = v / 8, jq = v % 8;
            float4 e4 = *(const float4*)&Eb[(size_t)i * Nn + jbase + jq * 4];
            es[jq*4+0][i] = e4.x; es[jq*4+1][i] = e4.y; es[jq*4+2][i] = e4.z; es[jq*4+3][i] = e4.w;
        }
        #pragma unroll
        for (int p = 0; p < 2; ++p) {
            int v = tid + 256 * p;
            int t = v / 8, jq = v % 8;
            float4 x4 = *(const float4*)&xb[(size_t)t * Nn + jbase + jq * 4];
            xs[jq*4+0][t] = x4.x; xs[jq*4+1][t] = x4.y; xs[jq*4+2][t] = x4.z; xs[jq*4+3][t] = x4.w;
        }
        __syncthreads();
        #pragma unroll
        for (int jj = 0; jj < 32; ++jj) {
            float4 xv = *(float4*)&xs[jj][tt * 4];
            float4 elo = *(float4*)&es[jj][it * 8];
            float4 ehi = *(float4*)&es[jj][it * 8 + 4];
            float ev[8] = {elo.x, elo.y, elo.z, elo.w, ehi.x, ehi.y, ehi.z, ehi.w};
            #pragma unroll
            for (int i = 0; i < 8; ++i) {
                acc[i].x += ev[i]*xv.x; acc[i].y += ev[i]*xv.y;
                acc[i].z += ev[i]*xv.z; acc[i].w += ev[i]*xv.w;
            }
        }
        __syncthreads();
    }
    #pragma unroll
    for (int i = 0; i < 8; ++i) {
        int gi = ibase + it * 8 + i;
        atomicAdd(&g_AGG[((tt*4+0) * Bb + b) * Nn + gi], acc[i].x);
        atomicAdd(&g_AGG[((tt*4+1) * Bb + b) * Nn + gi], acc[i].y);
        atomicAdd(&g_AGG[((tt*4+2) * Bb + b) * Nn + gi], acc[i].z);
        atomicAdd(&g_AGG[((tt*4+3) * Bb + b) * Nn + gi], acc[i].w);
    }
}

// ---------------- K5: gate GEMM partials per step ----------------
// part[g][ks][b][n] = sum_{k in split} h[b,k]*Wg[n,k]; tile 128n x 16b x 128k.
__global__ __launch_bounds__(64) void k5_lin(
    const float* __restrict__ Whr, const float* __restrict__ Whz,
    const float* __restrict__ Whn)
{
    const float* W = (blockIdx.z == 0) ? Whr : ((blockIdx.z == 1) ? Whz : Whn);
    __shared__ float ws[32][132];
    __shared__ float hs[32][20];
    int tid = threadIdx.x;
    int nbase = blockIdx.y * 128;
    int kbase0 = blockIdx.x * 128;
    int nt = tid % 16, bt = tid / 16;

    float4 acc[8];
    #pragma unroll
    for (int i = 0; i < 8; ++i) acc[i] = make_float4(0,0,0,0);

    for (int kc = 0; kc < 4; ++kc) {
        int kbase = kbase0 + kc * 32;
        #pragma unroll
        for (int p = 0; p < 16; ++p) {
            int v = tid + 64 * p;
            int n = v / 8, kq = v % 8;
            float4 w4 = *(const float4*)&W[(size_t)(nbase + n) * Nn + kbase + kq * 4];
            ws[kq*4+0][n] = w4.x; ws[kq*4+1][n] = w4.y; ws[kq*4+2][n] = w4.z; ws[kq*4+3][n] = w4.w;
        }
        #pragma unroll
        for (int p = 0; p < 2; ++p) {
            int v = tid + 64 * p;
            int bb = v / 8, kq = v % 8;
            float4 h4 = *(const float4*)&g_h[bb * Nn + kbase + kq * 4];
            hs[kq*4+0][bb] = h4.x; hs[kq*4+1][bb] = h4.y; hs[kq*4+2][bb] = h4.z; hs[kq*4+3][bb] = h4.w;
        }
        __syncthreads();
        #pragma unroll
        for (int kk = 0; kk < 32; ++kk) {
            float4 hv  = *(float4*)&hs[kk][bt * 4];
            float4 wlo = *(float4*)&ws[kk][nt * 8];
            float4 whi = *(float4*)&ws[kk][nt * 8 + 4];
            float wv[8] = {wlo.x, wlo.y, wlo.z, wlo.w, whi.x, whi.y, whi.z, whi.w};
            #pragma unroll
            for (int ni = 0; ni < 8; ++ni) {
                acc[ni].x += wv[ni]*hv.x; acc[ni].y += wv[ni]*hv.y;
                acc[ni].z += wv[ni]*hv.z; acc[ni].w += wv[ni]*hv.w;
            }
        }
        __syncthreads();
    }
    float* P = g_part + ((size_t)(blockIdx.z * KSPLIT + blockIdx.x) * Bb) * Nn;
    #pragma unroll
    for (int ni = 0; ni < 8; ++ni) {
        int n = nbase + nt * 8 + ni;
        P[(bt*4+0) * Nn + n] = acc[ni].x;
        P[(bt*4+1) * Nn + n] = acc[ni].y;
        P[(bt*4+2) * Nn + n] = acc[ni].z;
        P[(bt*4+3) * Nn + n] = acc[ni].w;
    }
}

// ---------------- K6: gate elementwise + partial reduce + h update ----------------
__global__ void k6_gate(const float* __restrict__ bhr, const float* __restrict__ bhz,
                        const float* __restrict__ bhn, int t)
{
    int idx = blockIdx.x * 256 + threadIdx.x;
    if (idx >= Bb * Nn) return;
    int i = idx % Nn;
    float rl = bhr[i], zl = bhz[i], nl = bhn[i];
    #pragma unroll
    for (int p = 0; p < KSPLIT; ++p) {
        rl += g_part[(size_t)(0 * KSPLIT + p) * (Bb * Nn) + idx];
        zl += g_part[(size_t)(1 * KSPLIT + p) * (Bb * Nn) + idx];
        nl += g_part[(size_t)(2 * KSPLIT + p) * (Bb * Nn) + idx];
    }
    float agg = g_AGG[(size_t)t * (Bb * Nn) + idx];
    float h = g_h[idx];
    float r = 1.f / (1.f + expf(-(agg + rl)));
    float z = 1.f / (1.f + expf(-(agg + zl)));
    float n = tanhf(agg + r * nl);
    g_h[idx] = (1.f - z) * n + z * h;
}

// ---------------- K7: out[b] = h[b,:].Wo + bo ----------------
__global__ void k7_out(const float* __restrict__ Wo, const float* __restrict__ bo,
                       float* __restrict__ out)
{
    __shared__ float red[256];
    int b = blockIdx.x, tid = threadIdx.x;
    float s = 0.f;
    for (int i = tid; i < Nn; i += 256) s += g_h[b * Nn + i] * Wo[i];
    red[tid] = s;
    __syncthreads();
    for (int off = 128; off > 0; off >>= 1) {
        if (tid < off) red[tid] += red[tid + off];
        __syncthreads();
    }
    if (tid == 0) out[b] = red[0] + bo[0];
}

extern "C" void kernel_launch(void* const* d_in, const int* in_sizes, int n_in,
                              void* d_out, int out_size) {
    const float* x   = (const float*)d_in[0];
    const int*   adj = (const int*)  d_in[1];
    const float* Wq  = (const float*)d_in[2];
    const float* bq  = (const float*)d_in[3];
    const float* Wk  = (const float*)d_in[4];
    const float* bk  = (const float*)d_in[5];
    const float* Whr = (const float*)d_in[6];
    const float* bhr = (const float*)d_in[7];
    const float* Whz = (const float*)d_in[8];
    const float* bhz = (const float*)d_in[9];
    const float* Whn = (const float*)d_in[10];
    const float* bhn = (const float*)d_in[11];
    const float* Wo  = (const float*)d_in[12];
    const float* bo  = (const float*)d_in[13];
    float* out = (float*)d_out;

    // zero scratch (cs, h, AGG)
    k0_zero<<<(Ss * Bb * Nn + 255) / 256, 256>>>();

    // Q,K projection
    k1_qk<<<dim3(Nn / 128, Ee / 64, Bb), 256>>>(x, Wq, bq, Wk, bk);

    // scores + mask + exp + column sums
    k2_scores<<<dim3(Nn / 128, Nn / 128, Bb), 256>>>(adj);

    // normalized x
    k3_xn<<<(Bb * Ss * Nn + 255) / 256, 256>>>(x);

    // all-timestep aggregates
    k4_agg<<<dim3(Nn / 128, 2, Bb), 256>>>();

    // GRU recurrence
    for (int t = 0; t < Ss; ++t) {
        k5_lin<<<dim3(KSPLIT, Nn / 128, 3), 64>>>(Whr, Whz, Whn);
        k6_gate<<<(Bb * Nn + 255) / 256, 256>>>(bhr, bhz, bhn, t);
    }

    // output head
    k7_out<<<Bb, 256>>>(Wo, bo, out);
}